// round 12
// baseline (speedup 1.0000x reference)
#include <cuda_runtime.h>

// z_hat [B,T,D] f32, P [B,T] f32, lengths [B] i32 -> out [B,T,D] f32
#define BB 4
#define TT 4096
#define DD 512
#define CC 512              // chunks along T
#define LL 8                // chunk length
#define D4 128              // float4 lanes per row (DD/4)
#define NCHUNK (BB*CC)      // 2048 chunks, f = b*CC + c

// Scratch (__device__ globals; allocation-free rule). idx f = b*CC + c.
__device__ float g_Bsum[NCHUNK * DD];
__device__ float g_A[NCHUNK];
__device__ float g_Zinit[NCHUNK * DD];

// Volatile vector load: ptxas cannot sink it or collapse its destination
// registers -> all issued loads are genuinely in flight together.
__device__ __forceinline__ float4 ldg128(const float4* p)
{
    float4 v;
    asm volatile("ld.global.nc.v4.f32 {%0,%1,%2,%3}, [%4];"
                 : "=f"(v.x), "=f"(v.y), "=f"(v.z), "=f"(v.w) : "l"(p));
    return v;
}

// ---------------------------------------------------------------------------
// K1: per-chunk weighted reduction.
// The 8 z row-loads are issued first as volatile PTX loads (guaranteed MLP=8);
// P loads + the weight chain execute while they are in flight.
// ---------------------------------------------------------------------------
__global__ void __launch_bounds__(128, 8) k1_chunk_summary(
    const float* __restrict__ z, const float* __restrict__ P,
    const int* __restrict__ lengths)
{
    const int b = blockIdx.x;     // fastest -> masked/active mixed across SMs
    const int c = blockIdx.y;
    const int lane = threadIdx.x; // float4 lane over D
    const int len = lengths[b];
    const int t0 = c * LL;
    if (t0 >= len) return;        // masked chunk: state never consumed

    const float4* zp = (const float4*)(z + ((size_t)b * TT + t0) * DD);

    // ---- 8 independent volatile loads, all in flight before anything else ----
    float4 x0 = ldg128(zp + 0 * D4 + lane);
    float4 x1 = ldg128(zp + 1 * D4 + lane);
    float4 x2 = ldg128(zp + 2 * D4 + lane);
    float4 x3 = ldg128(zp + 3 * D4 + lane);
    float4 x4 = ldg128(zp + 4 * D4 + lane);
    float4 x5 = ldg128(zp + 5 * D4 + lane);
    float4 x6 = ldg128(zp + 6 * D4 + lane);
    float4 x7 = ldg128(zp + 7 * D4 + lane);

    // ---- P loads + weight chain overlap with the z loads ----
    float pcl[LL];
#pragma unroll
    for (int k = 0; k < LL; ++k) {
        float p = __ldg(&P[b * TT + t0 + k]);     // warp-uniform broadcast
        pcl[k] = fminf(fmaxf(p, 0.0f), 1.0f - 1e-6f);
    }
    float w[LL];
    float r = 1.0f;
#pragma unroll
    for (int k = LL - 1; k >= 0; --k) {
        w[k] = fmaxf(pcl[k], 1e-6f) * r;          // w[k]=pe[k]*prod_{m>k}q[m]
        r *= (1.0f - pcl[k]);
    }

    float4 a0, a1;
    a0.x = w[0] * x0.x; a0.y = w[0] * x0.y; a0.z = w[0] * x0.z; a0.w = w[0] * x0.w;
    a1.x = w[1] * x1.x; a1.y = w[1] * x1.y; a1.z = w[1] * x1.z; a1.w = w[1] * x1.w;
    a0.x = fmaf(w[2], x2.x, a0.x); a0.y = fmaf(w[2], x2.y, a0.y);
    a0.z = fmaf(w[2], x2.z, a0.z); a0.w = fmaf(w[2], x2.w, a0.w);
    a1.x = fmaf(w[3], x3.x, a1.x); a1.y = fmaf(w[3], x3.y, a1.y);
    a1.z = fmaf(w[3], x3.z, a1.z); a1.w = fmaf(w[3], x3.w, a1.w);
    a0.x = fmaf(w[4], x4.x, a0.x); a0.y = fmaf(w[4], x4.y, a0.y);
    a0.z = fmaf(w[4], x4.z, a0.z); a0.w = fmaf(w[4], x4.w, a0.w);
    a1.x = fmaf(w[5], x5.x, a1.x); a1.y = fmaf(w[5], x5.y, a1.y);
    a1.z = fmaf(w[5], x5.z, a1.z); a1.w = fmaf(w[5], x5.w, a1.w);
    a0.x = fmaf(w[6], x6.x, a0.x); a0.y = fmaf(w[6], x6.y, a0.y);
    a0.z = fmaf(w[6], x6.z, a0.z); a0.w = fmaf(w[6], x6.w, a0.w);
    a1.x = fmaf(w[7], x7.x, a1.x); a1.y = fmaf(w[7], x7.y, a1.y);
    a1.z = fmaf(w[7], x7.z, a1.z); a1.w = fmaf(w[7], x7.w, a1.w);

    const int f = b * CC + c;
    ((float4*)g_Bsum)[(size_t)f * D4 + lane] =
        make_float4(a0.x + a1.x, a0.y + a1.y, a0.z + a1.z, a0.w + a1.w);
    if (lane == 0) g_A[f] = r;
}

// ---------------------------------------------------------------------------
// K2: parallel cross-chunk scan (pair-combined Hillis-Steele over affine
// maps). Block = (b, d4-lane g); thread i owns chunk pair (2i, 2i+1).
// Composition (A2,B2)∘(A1,B1)=(A2*A1, A2*B1+B2). Garbage in masked chunks
// only flows toward higher c -> never consumed.
// ---------------------------------------------------------------------------
__global__ void __launch_bounds__(256) k2_scan()
{
    const int b = blockIdx.x;
    const int g = blockIdx.y;     // d4 lane 0..127
    const int i = threadIdx.x;    // pair id 0..255

    const int f0 = b * CC + 2 * i;
    const int f1 = f0 + 1;

    float a0 = g_A[f0];
    float a1 = g_A[f1];
    float4 v0 = ((const float4*)g_Bsum)[(size_t)f0 * D4 + g];
    float4 v1 = ((const float4*)g_Bsum)[(size_t)f1 * D4 + g];

    float  ac = a1 * a0;
    float4 bc = make_float4(fmaf(a1, v0.x, v1.x), fmaf(a1, v0.y, v1.y),
                            fmaf(a1, v0.z, v1.z), fmaf(a1, v0.w, v1.w));

    __shared__ float sA[256];
    __shared__ float4 sB[256];
    sA[i] = ac; sB[i] = bc;
    __syncthreads();
#pragma unroll
    for (int s = 1; s < 256; s <<= 1) {
        float pa = 1.0f;
        float4 pb = make_float4(0.f, 0.f, 0.f, 0.f);
        if (i >= s) { pa = sA[i - s]; pb = sB[i - s]; }
        __syncthreads();
        if (i >= s) {
            bc.x = fmaf(ac, pb.x, bc.x);
            bc.y = fmaf(ac, pb.y, bc.y);
            bc.z = fmaf(ac, pb.z, bc.z);
            bc.w = fmaf(ac, pb.w, bc.w);
            ac *= pa;
            sA[i] = ac; sB[i] = bc;
        }
        __syncthreads();
    }
    float4 Eb = (i == 0) ? make_float4(0.f, 0.f, 0.f, 0.f) : sB[i - 1];
    float4* __restrict__ zi = (float4*)g_Zinit;
    zi[(size_t)f0 * D4 + g] = Eb;
    zi[(size_t)f1 * D4 + g] =
        make_float4(fmaf(a0, Eb.x, v0.x), fmaf(a0, Eb.y, v0.y),
                    fmaf(a0, Eb.z, v0.z), fmaf(a0, Eb.w, v0.w));
}

// ---------------------------------------------------------------------------
// K3: per-chunk local scan seeded with Zinit. Volatile-front-batched loads;
// NORMAL stores (L2 writeback; out fits L2 -> fast). Masked chunks zero-fill.
// ---------------------------------------------------------------------------
__global__ void __launch_bounds__(128, 8) k3_scan_out(
    const float* __restrict__ z, const float* __restrict__ P,
    const int* __restrict__ lengths, float* __restrict__ out)
{
    const int b = blockIdx.x;
    const int c = blockIdx.y;
    const int lane = threadIdx.x;
    const int len = lengths[b];
    const int t0 = c * LL;

    float4* __restrict__ op = (float4*)(out + ((size_t)b * TT + t0) * DD);

    if (t0 >= len) {                 // fully masked: zero-fill, no loads
        float4 zero = make_float4(0.f, 0.f, 0.f, 0.f);
#pragma unroll
        for (int k = 0; k < LL; ++k) op[(size_t)k * D4 + lane] = zero;
        return;
    }

    const float4* zp = (const float4*)(z + ((size_t)b * TT + t0) * DD);

    // ---- all loads in flight first: 8 z rows + carry ----
    float4 x0 = ldg128(zp + 0 * D4 + lane);
    float4 x1 = ldg128(zp + 1 * D4 + lane);
    float4 x2 = ldg128(zp + 2 * D4 + lane);
    float4 x3 = ldg128(zp + 3 * D4 + lane);
    float4 x4 = ldg128(zp + 4 * D4 + lane);
    float4 x5 = ldg128(zp + 5 * D4 + lane);
    float4 x6 = ldg128(zp + 6 * D4 + lane);
    float4 x7 = ldg128(zp + 7 * D4 + lane);
    float4 zv = ldg128((const float4*)g_Zinit + (size_t)(b * CC + c) * D4 + lane);

    float pcl[LL];
#pragma unroll
    for (int k = 0; k < LL; ++k) {
        float p = __ldg(&P[b * TT + t0 + k]);
        pcl[k] = fminf(fmaxf(p, 0.0f), 1.0f - 1e-6f);
    }

#pragma unroll
    for (int k = 0; k < LL; ++k) {
        float4 x = (k == 0) ? x0 : (k == 1) ? x1 : (k == 2) ? x2 : (k == 3) ? x3
                 : (k == 4) ? x4 : (k == 5) ? x5 : (k == 6) ? x6 : x7;
        float q = 1.0f - pcl[k];
        float pe = fmaxf(pcl[k], 1e-6f);
        zv.x = fmaf(q, zv.x, pe * x.x);
        zv.y = fmaf(q, zv.y, pe * x.y);
        zv.z = fmaf(q, zv.z, pe * x.z);
        zv.w = fmaf(q, zv.w, pe * x.w);
        float m = (t0 + k < len) ? 1.0f : 0.0f;
        op[(size_t)k * D4 + lane] =
            make_float4(zv.x * m, zv.y * m, zv.z * m, zv.w * m);
    }
}

extern "C" void kernel_launch(void* const* d_in, const int* in_sizes, int n_in,
                              void* d_out, int out_size)
{
    const float* z = (const float*)d_in[0];
    const float* P = (const float*)d_in[1];
    const int* lengths = (const int*)d_in[2];
    float* out = (float*)d_out;

    dim3 gridA(BB, CC);        // b fastest -> masked/active mixed across SMs
    k1_chunk_summary<<<gridA, 128>>>(z, P, lengths);
    dim3 gridS(BB, D4);
    k2_scan<<<gridS, 256>>>();
    k3_scan_out<<<gridA, 128>>>(z, P, lengths, out);
}

// round 13
// speedup vs baseline: 1.0085x; 1.0085x over previous
#include <cuda_runtime.h>

// z_hat [B,T,D] f32, P [B,T] f32, lengths [B] i32 -> out [B,T,D] f32
#define BB 4
#define TT 4096
#define DD 512
#define CC 256              // chunks along T  (best-known config)
#define LL 16               // chunk length
#define D4 128              // float4 lanes per row (DD/4)
#define NCHUNK (BB*CC)      // 1024 chunks, f = b*CC + c
#define NSCAN 512           // scan instances = BB * D4

// Scratch (__device__ globals; allocation-free rule). idx f = b*CC + c.
__device__ float g_Bsum[NCHUNK * DD];
__device__ float g_A[NCHUNK];
__device__ float g_Zinit[NCHUNK * DD];
__device__ unsigned g_ctr;   // monotonic; each launch adds exactly NCHUNK
                             // (wrap-safe: 2^32 % 1024 == 0) -> deterministic

// ---------------------------------------------------------------------------
// kA = K1 (per-chunk weighted reduction) + embedded K2 (cross-chunk scan).
// After a block publishes its summary it takes a ticket. The last NSCAN
// ticket-holders (still resident; ALL 1024 blocks fit on-chip concurrently,
// so the spin cannot deadlock) wait for every ticket, then each runs one
// (b, d4-lane) scan instance over the CC chunk maps.
// ---------------------------------------------------------------------------
__global__ void __launch_bounds__(128, 8) kA_summary_scan(
    const float* __restrict__ z, const float* __restrict__ P,
    const int* __restrict__ lengths)
{
    const int b = blockIdx.x;     // fastest -> masked/active mixed across SMs
    const int c = blockIdx.y;
    const int lane = threadIdx.x; // float4 lane over D
    const int len = lengths[b];
    const int t0 = c * LL;

    // ---------------- Phase A: chunk summary (skip if masked) ----------------
    if (t0 < len) {
        float pcl[LL];
#pragma unroll
        for (int k = 0; k < LL; ++k) {
            float p = __ldg(&P[b * TT + t0 + k]);     // warp-uniform broadcast
            pcl[k] = fminf(fmaxf(p, 0.0f), 1.0f - 1e-6f);
        }
        float w[LL];
        float r = 1.0f;
#pragma unroll
        for (int k = LL - 1; k >= 0; --k) {
            w[k] = fmaxf(pcl[k], 1e-6f) * r;   // w[k]=pe[k]*prod_{m>k}q[m]
            r *= (1.0f - pcl[k]);
        }

        const float4* __restrict__ zp =
            (const float4*)(z + ((size_t)b * TT + t0) * DD);
        float4 a0 = make_float4(0.f, 0.f, 0.f, 0.f);
        float4 a1 = make_float4(0.f, 0.f, 0.f, 0.f);
#pragma unroll
        for (int kb = 0; kb < LL; kb += 8) {
            float4 x0 = zp[(size_t)(kb + 0) * D4 + lane];
            float4 x1 = zp[(size_t)(kb + 1) * D4 + lane];
            float4 x2 = zp[(size_t)(kb + 2) * D4 + lane];
            float4 x3 = zp[(size_t)(kb + 3) * D4 + lane];
            float4 x4 = zp[(size_t)(kb + 4) * D4 + lane];
            float4 x5 = zp[(size_t)(kb + 5) * D4 + lane];
            float4 x6 = zp[(size_t)(kb + 6) * D4 + lane];
            float4 x7 = zp[(size_t)(kb + 7) * D4 + lane];
            asm volatile("" ::: "memory");
            a0.x = fmaf(w[kb+0], x0.x, a0.x); a0.y = fmaf(w[kb+0], x0.y, a0.y);
            a0.z = fmaf(w[kb+0], x0.z, a0.z); a0.w = fmaf(w[kb+0], x0.w, a0.w);
            a1.x = fmaf(w[kb+1], x1.x, a1.x); a1.y = fmaf(w[kb+1], x1.y, a1.y);
            a1.z = fmaf(w[kb+1], x1.z, a1.z); a1.w = fmaf(w[kb+1], x1.w, a1.w);
            a0.x = fmaf(w[kb+2], x2.x, a0.x); a0.y = fmaf(w[kb+2], x2.y, a0.y);
            a0.z = fmaf(w[kb+2], x2.z, a0.z); a0.w = fmaf(w[kb+2], x2.w, a0.w);
            a1.x = fmaf(w[kb+3], x3.x, a1.x); a1.y = fmaf(w[kb+3], x3.y, a1.y);
            a1.z = fmaf(w[kb+3], x3.z, a1.z); a1.w = fmaf(w[kb+3], x3.w, a1.w);
            a0.x = fmaf(w[kb+4], x4.x, a0.x); a0.y = fmaf(w[kb+4], x4.y, a0.y);
            a0.z = fmaf(w[kb+4], x4.z, a0.z); a0.w = fmaf(w[kb+4], x4.w, a0.w);
            a1.x = fmaf(w[kb+5], x5.x, a1.x); a1.y = fmaf(w[kb+5], x5.y, a1.y);
            a1.z = fmaf(w[kb+5], x5.z, a1.z); a1.w = fmaf(w[kb+5], x5.w, a1.w);
            a0.x = fmaf(w[kb+6], x6.x, a0.x); a0.y = fmaf(w[kb+6], x6.y, a0.y);
            a0.z = fmaf(w[kb+6], x6.z, a0.z); a0.w = fmaf(w[kb+6], x6.w, a0.w);
            a1.x = fmaf(w[kb+7], x7.x, a1.x); a1.y = fmaf(w[kb+7], x7.y, a1.y);
            a1.z = fmaf(w[kb+7], x7.z, a1.z); a1.w = fmaf(w[kb+7], x7.w, a1.w);
        }
        const int f = b * CC + c;
        ((float4*)g_Bsum)[(size_t)f * D4 + lane] =
            make_float4(a0.x + a1.x, a0.y + a1.y, a0.z + a1.z, a0.w + a1.w);
        if (lane == 0) g_A[f] = r;
    }

    // ---------------- Ticket: last NSCAN blocks run the scan ----------------
    __shared__ int s_scan_id;
    __threadfence();                         // publish Bsum/A before ticket
    if (lane == 0) {
        unsigned old = atomicAdd(&g_ctr, 1u);
        unsigned t = old & (NCHUNK - 1u);    // ticket within this launch
        int id = (int)t - (NCHUNK - NSCAN);  // >=0 for the last NSCAN tickets
        s_scan_id = id;
        if (id >= 0) {
            unsigned target = old - t + NCHUNK;   // all tickets of this launch
            volatile unsigned* p = &g_ctr;
            while ((int)(*p - target) < 0) { }
            __threadfence();
        }
    }
    __syncthreads();
    const int sid = s_scan_id;
    if (sid < 0) return;

    // ---------------- Phase B: scan instance (sb, g) ----------------
    // Pair-combined Hillis-Steele over CC=256 affine maps (verified R7).
    // Composition (A2,B2)∘(A1,B1) = (A2*A1, A2*B1+B2).
    {
        const int sb = sid & (BB - 1);
        const int g  = sid >> 2;             // d4 lane 0..127
        const int i  = lane;                 // pair id 0..127
        const int f0 = sb * CC + 2 * i;
        const int f1 = f0 + 1;

        float a0 = g_A[f0];
        float a1 = g_A[f1];
        float4 v0 = ((const float4*)g_Bsum)[(size_t)f0 * D4 + g];
        float4 v1 = ((const float4*)g_Bsum)[(size_t)f1 * D4 + g];

        float  ac = a1 * a0;
        float4 bc = make_float4(fmaf(a1, v0.x, v1.x), fmaf(a1, v0.y, v1.y),
                                fmaf(a1, v0.z, v1.z), fmaf(a1, v0.w, v1.w));

        __shared__ float sA[128];
        __shared__ float4 sB[128];
        sA[i] = ac; sB[i] = bc;
        __syncthreads();
#pragma unroll
        for (int s = 1; s < 128; s <<= 1) {
            float pa = 1.0f;
            float4 pb = make_float4(0.f, 0.f, 0.f, 0.f);
            if (i >= s) { pa = sA[i - s]; pb = sB[i - s]; }
            __syncthreads();
            if (i >= s) {
                bc.x = fmaf(ac, pb.x, bc.x);
                bc.y = fmaf(ac, pb.y, bc.y);
                bc.z = fmaf(ac, pb.z, bc.z);
                bc.w = fmaf(ac, pb.w, bc.w);
                ac *= pa;
                sA[i] = ac; sB[i] = bc;
            }
            __syncthreads();
        }
        float4 Eb = (i == 0) ? make_float4(0.f, 0.f, 0.f, 0.f) : sB[i - 1];
        float4* __restrict__ zi = (float4*)g_Zinit;
        zi[(size_t)f0 * D4 + g] = Eb;
        zi[(size_t)f1 * D4 + g] =
            make_float4(fmaf(a0, Eb.x, v0.x), fmaf(a0, Eb.y, v0.y),
                        fmaf(a0, Eb.z, v0.z), fmaf(a0, Eb.w, v0.w));
    }
}

// ---------------------------------------------------------------------------
// kB = K3: per-chunk local scan seeded with Zinit; mask; write out.
// (Exact structure of the 17.15us R5 kernel.) Masked chunks zero-fill.
// ---------------------------------------------------------------------------
__global__ void __launch_bounds__(128, 8) kB_scan_out(
    const float* __restrict__ z, const float* __restrict__ P,
    const int* __restrict__ lengths, float* __restrict__ out)
{
    const int b = blockIdx.x;
    const int c = blockIdx.y;
    const int lane = threadIdx.x;
    const int len = lengths[b];
    const int t0 = c * LL;

    float4* __restrict__ op = (float4*)(out + ((size_t)b * TT + t0) * DD);

    if (t0 >= len) {                 // fully masked: zero-fill, no loads
        float4 zero = make_float4(0.f, 0.f, 0.f, 0.f);
#pragma unroll
        for (int k = 0; k < LL; ++k) op[(size_t)k * D4 + lane] = zero;
        return;
    }

    // carry load issued early (latency hidden behind P loads)
    float4 zv = ((const float4*)g_Zinit)[(size_t)(b * CC + c) * D4 + lane];

    float pcl[LL];
#pragma unroll
    for (int k = 0; k < LL; ++k) {
        float p = __ldg(&P[b * TT + t0 + k]);
        pcl[k] = fminf(fmaxf(p, 0.0f), 1.0f - 1e-6f);
    }

    const float4* __restrict__ zp =
        (const float4*)(z + ((size_t)b * TT + t0) * DD);

#pragma unroll
    for (int kb = 0; kb < LL; kb += 8) {
        float4 x0 = zp[(size_t)(kb + 0) * D4 + lane];
        float4 x1 = zp[(size_t)(kb + 1) * D4 + lane];
        float4 x2 = zp[(size_t)(kb + 2) * D4 + lane];
        float4 x3 = zp[(size_t)(kb + 3) * D4 + lane];
        float4 x4 = zp[(size_t)(kb + 4) * D4 + lane];
        float4 x5 = zp[(size_t)(kb + 5) * D4 + lane];
        float4 x6 = zp[(size_t)(kb + 6) * D4 + lane];
        float4 x7 = zp[(size_t)(kb + 7) * D4 + lane];
        asm volatile("" ::: "memory");
#pragma unroll
        for (int u = 0; u < 8; ++u) {
            const int kk = kb + u;
            float4 x = (u == 0) ? x0 : (u == 1) ? x1 : (u == 2) ? x2 : (u == 3) ? x3
                     : (u == 4) ? x4 : (u == 5) ? x5 : (u == 6) ? x6 : x7;
            float q = 1.0f - pcl[kk];
            float pe = fmaxf(pcl[kk], 1e-6f);
            zv.x = fmaf(q, zv.x, pe * x.x);
            zv.y = fmaf(q, zv.y, pe * x.y);
            zv.z = fmaf(q, zv.z, pe * x.z);
            zv.w = fmaf(q, zv.w, pe * x.w);
            float m = (t0 + kk < len) ? 1.0f : 0.0f;
            op[(size_t)kk * D4 + lane] =
                make_float4(zv.x * m, zv.y * m, zv.z * m, zv.w * m);
        }
    }
}

extern "C" void kernel_launch(void* const* d_in, const int* in_sizes, int n_in,
                              void* d_out, int out_size)
{
    const float* z = (const float*)d_in[0];
    const float* P = (const float*)d_in[1];
    const int* lengths = (const int*)d_in[2];
    float* out = (float*)d_out;

    dim3 grid(BB, CC);         // b fastest -> masked/active mixed across SMs
    kA_summary_scan<<<grid, 128>>>(z, P, lengths);
    kB_scan_out<<<grid, 128>>>(z, P, lengths, out);
}